// round 13
// baseline (speedup 1.0000x reference)
#include <cuda_runtime.h>
#include <cuda_fp16.h>
#include <cstdint>

// GraphConv: out = relu( segment_sum(feature[src] -> dst) @ W^T + b )
// R13: R12 + issue-optimized gather (int4 bin loads, fp16 HADD2 4-edge tree,
//      fp32 group flush).

constexpr int N_NODES = 50000;
constexpr int N_EDGES = 800000;
constexpr int D       = 128;
constexpr int CAP     = 128;

// ---- static scratch ----
__device__ __half g_h16[N_NODES * D];        // 12.8 MB h = fp16(feature @ W^T)
__device__ uint4  g_wfrag[8 * 8 * 32];       // 32 KB fragment-major fp16 W
__device__ int    g_bins[N_NODES * CAP];     // 25.6 MB binned src ids
__device__ int    g_cursor[N_NODES];         // fill cursor == in-degree
__device__ int    g_ovf_cnt;
__device__ int2   g_ovf[N_EDGES];            // overflow edges (correctness net)

// ---------------------------------------------------------------------------
// 1) prep: build fragment-major fp16 W table + zero cursors (see R11 notes)
// ---------------------------------------------------------------------------
__device__ __forceinline__ uint32_t pack_h2(float a, float b) {
    __half2 h = __floats2half2_rn(a, b);
    return *reinterpret_cast<uint32_t*>(&h);
}

__global__ void __launch_bounds__(256) prep_kernel(const float* __restrict__ Wm)
{
    int i = blockIdx.x * blockDim.x + threadIdx.x;
    if (i < 2048) {
        int ks   = i >> 8;
        int np   = (i >> 5) & 7;
        int lane = i & 31;
        int gp   = lane >> 2;
        int tg   = lane & 3;
        int k0   = 16 * ks + 2 * tg;
        int n0   = 16 * np + gp;
        uint4 v;
        v.x = pack_h2(Wm[n0 * D + k0    ], Wm[n0 * D + k0 + 1]);
        v.y = pack_h2(Wm[n0 * D + k0 + 8], Wm[n0 * D + k0 + 9]);
        v.z = pack_h2(Wm[(n0 + 8) * D + k0    ], Wm[(n0 + 8) * D + k0 + 1]);
        v.w = pack_h2(Wm[(n0 + 8) * D + k0 + 8], Wm[(n0 + 8) * D + k0 + 9]);
        g_wfrag[i] = v;
    }
    if (i < N_NODES) g_cursor[i] = 0;
    if (i == 0) g_ovf_cnt = 0;
}

// ---------------------------------------------------------------------------
// 2) bin fill: 4 edges per thread (MLP=4)
// ---------------------------------------------------------------------------
__device__ __forceinline__ void fill_one(int src, int dst, int pos) {
    if (pos < CAP) {
        g_bins[dst * CAP + pos] = src;
    } else {
        int o = atomicAdd(&g_ovf_cnt, 1);
        g_ovf[o] = make_int2(src, dst);
    }
}

__global__ void __launch_bounds__(256) fill_kernel(const int* __restrict__ ei)
{
    int i = blockIdx.x * blockDim.x + threadIdx.x;
    if (i >= N_EDGES / 4) return;
    int4 s = reinterpret_cast<const int4*>(ei)[i];
    int4 d = reinterpret_cast<const int4*>(ei + N_EDGES)[i];
    int p0 = atomicAdd(&g_cursor[d.x], 1);
    int p1 = atomicAdd(&g_cursor[d.y], 1);
    int p2 = atomicAdd(&g_cursor[d.z], 1);
    int p3 = atomicAdd(&g_cursor[d.w], 1);
    fill_one(s.x, d.x, p0);
    fill_one(s.y, d.y, p1);
    fill_one(s.z, d.z, p2);
    fill_one(s.w, d.w, p3);
}

// ---------------------------------------------------------------------------
// 3) gemm: h16 = fp16( feature @ W^T ).  No smem, no syncs. (R12, unchanged)
// ---------------------------------------------------------------------------
__device__ __forceinline__ void mma_f16(
    float& d0, float& d1, float& d2, float& d3,
    uint32_t a0, uint32_t a1, uint32_t a2, uint32_t a3,
    uint32_t b0, uint32_t b1)
{
    asm volatile(
        "mma.sync.aligned.m16n8k16.row.col.f32.f16.f16.f32 "
        "{%0,%1,%2,%3}, {%4,%5,%6,%7}, {%8,%9}, {%0,%1,%2,%3};"
        : "+f"(d0), "+f"(d1), "+f"(d2), "+f"(d3)
        : "r"(a0), "r"(a1), "r"(a2), "r"(a3), "r"(b0), "r"(b1));
}

__global__ void __launch_bounds__(128) gemm_h_kernel(const float* __restrict__ feat)
{
    int gw = (blockIdx.x * blockDim.x + threadIdx.x) >> 5;   // warp id
    if (gw >= N_NODES / 16) return;                          // 3125 warps exactly
    int lane = threadIdx.x & 31;
    int gp   = lane >> 2;
    int tg   = lane & 3;
    int r0   = gw * 16 + gp;                                 // rows r0, r0+8

    float acc[16][4];
#pragma unroll
    for (int nt = 0; nt < 16; nt++)
#pragma unroll
        for (int j = 0; j < 4; j++) acc[nt][j] = 0.f;

#pragma unroll
    for (int ks = 0; ks < 8; ks++) {
        int k0 = 16 * ks + 2 * tg;
        float2 f0 = *reinterpret_cast<const float2*>(feat + (r0    ) * D + k0    );
        float2 f1 = *reinterpret_cast<const float2*>(feat + (r0 + 8) * D + k0    );
        float2 f2 = *reinterpret_cast<const float2*>(feat + (r0    ) * D + k0 + 8);
        float2 f3 = *reinterpret_cast<const float2*>(feat + (r0 + 8) * D + k0 + 8);
        uint32_t a0 = pack_h2(f0.x, f0.y);
        uint32_t a1 = pack_h2(f1.x, f1.y);
        uint32_t a2 = pack_h2(f2.x, f2.y);
        uint32_t a3 = pack_h2(f3.x, f3.y);
#pragma unroll
        for (int np = 0; np < 8; np++) {
            uint4 b = g_wfrag[ks * 256 + np * 32 + lane];
            mma_f16(acc[2 * np][0], acc[2 * np][1], acc[2 * np][2], acc[2 * np][3],
                    a0, a1, a2, a3, b.x, b.y);
            mma_f16(acc[2 * np + 1][0], acc[2 * np + 1][1],
                    acc[2 * np + 1][2], acc[2 * np + 1][3],
                    a0, a1, a2, a3, b.z, b.w);
        }
    }

#pragma unroll
    for (int nt = 0; nt < 16; nt++) {
        int c = nt * 8 + 2 * tg;
        *reinterpret_cast<uint32_t*>(g_h16 + (r0    ) * D + c) =
            pack_h2(acc[nt][0], acc[nt][1]);
        *reinterpret_cast<uint32_t*>(g_h16 + (r0 + 8) * D + c) =
            pack_h2(acc[nt][2], acc[nt][3]);
    }
}

// ---------------------------------------------------------------------------
// 4) gather: warp-per-node over h16.  Groups of 4 edges: int4 bin load,
//    fp16 HADD2 tree, single fp32 flush.  + bias, relu, write out.
// ---------------------------------------------------------------------------
__device__ __forceinline__ __half2 h2x(const uint2& u) {
    return *reinterpret_cast<const __half2*>(&u.x);
}
__device__ __forceinline__ __half2 h2y(const uint2& u) {
    return *reinterpret_cast<const __half2*>(&u.y);
}

__device__ __forceinline__ void acc_add(float4& a, uint2 u) {
    float2 f0 = __half22float2(h2x(u));
    float2 f1 = __half22float2(h2y(u));
    a.x += f0.x; a.y += f0.y; a.z += f1.x; a.w += f1.y;
}

__global__ void __launch_bounds__(256) gather_kernel(
    const float* __restrict__ bias, float* __restrict__ out)
{
    int warp = (blockIdx.x * blockDim.x + threadIdx.x) >> 5;
    int lane = threadIdx.x & 31;
    if (warp >= N_NODES) return;

    const uint2* f = reinterpret_cast<const uint2*>(g_h16);   // 32 uint2/row

    int degf = g_cursor[warp];
    int deg  = min(degf, CAP);
    const int4* bin4 = reinterpret_cast<const int4*>(&g_bins[warp * CAP]);

    float4 acc = make_float4(0.f, 0.f, 0.f, 0.f);

    int ng = deg >> 2;                       // full groups of 4
    for (int g = 0; g < ng; g++) {
        int4 s = bin4[g];                    // 1 broadcast LDG.128
        uint2 u0 = f[s.x * 32 + lane];
        uint2 u1 = f[s.y * 32 + lane];
        uint2 u2 = f[s.z * 32 + lane];
        uint2 u3 = f[s.w * 32 + lane];
        // fp16 pairwise tree (sums of 4: |v|~2.3 max typical, fp16-safe)
        __half2 sx = __hadd2(__hadd2(h2x(u0), h2x(u1)), __hadd2(h2x(u2), h2x(u3)));
        __half2 sy = __hadd2(__hadd2(h2y(u0), h2y(u1)), __hadd2(h2y(u2), h2y(u3)));
        float2 fx = __half22float2(sx);
        float2 fy = __half22float2(sy);
        acc.x += fx.x; acc.y += fx.y; acc.z += fy.x; acc.w += fy.y;
    }
    for (int e = ng * 4; e < deg; e++) {     // tail (<=3 edges), exact path
        uint2 u = f[g_bins[warp * CAP + e] * 32 + lane];
        acc_add(acc, u);
    }

    if (degf > CAP) {                 // inline overflow fixup (expected never)
        int cnt = g_ovf_cnt;
        for (int j = 0; j < cnt; j++) {
            int2 sd = g_ovf[j];
            if (sd.y == warp) {
                uint2 u = f[sd.x * 32 + lane];
                acc_add(acc, u);
            }
        }
    }

    float4 bv = *reinterpret_cast<const float4*>(bias + lane * 4);
    float4 r;
    r.x = fmaxf(acc.x + bv.x, 0.f);
    r.y = fmaxf(acc.y + bv.y, 0.f);
    r.z = fmaxf(acc.z + bv.z, 0.f);
    r.w = fmaxf(acc.w + bv.w, 0.f);
    reinterpret_cast<float4*>(out)[warp * 32 + lane] = r;
}

// ---------------------------------------------------------------------------
extern "C" void kernel_launch(void* const* d_in, const int* in_sizes, int n_in,
                              void* d_out, int out_size)
{
    const float* feature = (const float*)d_in[0];   // [50000,128]
    const float* Wm      = (const float*)d_in[1];   // [128,128]
    const float* bias    = (const float*)d_in[2];   // [128]
    const int*   ei      = (const int*)  d_in[3];   // [2,800000]
    float*       out     = (float*)d_out;           // [50000,128]

    (void)in_sizes; (void)n_in; (void)out_size;

    prep_kernel<<<(N_NODES + 255) / 256, 256>>>(Wm);
    fill_kernel<<<(N_EDGES / 4 + 255) / 256, 256>>>(ei);
    {
        int warps = N_NODES / 16;                   // 3125
        int blocks = (warps * 32 + 127) / 128;      // 782
        gemm_h_kernel<<<blocks, 128>>>(feature);
    }
    {
        int total_threads = N_NODES * 32;
        gather_kernel<<<(total_threads + 255) / 256, 256>>>(bias, out);
    }
}

// round 14
// speedup vs baseline: 1.1906x; 1.1906x over previous
#include <cuda_runtime.h>
#include <cuda_fp16.h>
#include <cstdint>

// GraphConv: out = relu( segment_sum(feature[src] -> dst) @ W^T + b )
// R14: 3-launch pipeline.
//   1) prep: fragment-major fp16 W table + zero cursors
//   2) fused: [blocks 0..390] gemm h16 = fp16(feature @ W^T)  (smem-free HMMA)
//             [blocks 391.. ] fill capacity-binned CSR        (independent!)
//   3) gather: warp-per-node over h16 (int4 bins, fp32 adds), + bias, relu

constexpr int N_NODES = 50000;
constexpr int N_EDGES = 800000;
constexpr int D       = 128;
constexpr int CAP     = 128;

constexpr int GEMM_WARPS  = N_NODES / 16;                 // 3125
constexpr int GEMM_BLOCKS = (GEMM_WARPS + 7) / 8;         // 391 (256 thr = 8 warps)
constexpr int FILL_BLOCKS = (N_EDGES / 4 + 255) / 256;    // 782

// ---- static scratch ----
__device__ __half g_h16[N_NODES * D];        // 12.8 MB h = fp16(feature @ W^T)
__device__ uint4  g_wfrag[8 * 8 * 32];       // 32 KB fragment-major fp16 W
__device__ int    g_bins[N_NODES * CAP];     // 25.6 MB binned src ids
__device__ int    g_cursor[N_NODES];         // fill cursor == in-degree
__device__ int    g_ovf_cnt;
__device__ int2   g_ovf[N_EDGES];            // overflow edges (correctness net)

// ---------------------------------------------------------------------------
// helpers
// ---------------------------------------------------------------------------
__device__ __forceinline__ uint32_t pack_h2(float a, float b) {
    __half2 h = __floats2half2_rn(a, b);
    return *reinterpret_cast<uint32_t*>(&h);
}

__device__ __forceinline__ void mma_f16(
    float& d0, float& d1, float& d2, float& d3,
    uint32_t a0, uint32_t a1, uint32_t a2, uint32_t a3,
    uint32_t b0, uint32_t b1)
{
    asm volatile(
        "mma.sync.aligned.m16n8k16.row.col.f32.f16.f16.f32 "
        "{%0,%1,%2,%3}, {%4,%5,%6,%7}, {%8,%9}, {%0,%1,%2,%3};"
        : "+f"(d0), "+f"(d1), "+f"(d2), "+f"(d3)
        : "r"(a0), "r"(a1), "r"(a2), "r"(a3), "r"(b0), "r"(b1));
}

// ---------------------------------------------------------------------------
// 1) prep: build g_wfrag + zero cursors (mapping validated R9-R12)
// ---------------------------------------------------------------------------
__global__ void __launch_bounds__(256) prep_kernel(const float* __restrict__ Wm)
{
    int i = blockIdx.x * blockDim.x + threadIdx.x;
    if (i < 2048) {
        int ks   = i >> 8;
        int np   = (i >> 5) & 7;
        int lane = i & 31;
        int gp   = lane >> 2;
        int tg   = lane & 3;
        int k0   = 16 * ks + 2 * tg;
        int n0   = 16 * np + gp;
        uint4 v;
        v.x = pack_h2(Wm[n0 * D + k0    ], Wm[n0 * D + k0 + 1]);
        v.y = pack_h2(Wm[n0 * D + k0 + 8], Wm[n0 * D + k0 + 9]);
        v.z = pack_h2(Wm[(n0 + 8) * D + k0    ], Wm[(n0 + 8) * D + k0 + 1]);
        v.w = pack_h2(Wm[(n0 + 8) * D + k0 + 8], Wm[(n0 + 8) * D + k0 + 9]);
        g_wfrag[i] = v;
    }
    if (i < N_NODES) g_cursor[i] = 0;
    if (i == 0) g_ovf_cnt = 0;
}

// ---------------------------------------------------------------------------
// 2) fused gemm + fill
// ---------------------------------------------------------------------------
__device__ __forceinline__ void fill_one(int src, int dst, int pos) {
    if (pos < CAP) {
        g_bins[dst * CAP + pos] = src;
    } else {
        int o = atomicAdd(&g_ovf_cnt, 1);
        g_ovf[o] = make_int2(src, dst);
    }
}

__device__ void gemm_warp_body(int gw, int lane, const float* __restrict__ feat)
{
    int gp = lane >> 2;
    int tg = lane & 3;
    int r0 = gw * 16 + gp;                                   // rows r0, r0+8

    float acc[16][4];
#pragma unroll
    for (int nt = 0; nt < 16; nt++)
#pragma unroll
        for (int j = 0; j < 4; j++) acc[nt][j] = 0.f;

#pragma unroll
    for (int ks = 0; ks < 8; ks++) {
        int k0 = 16 * ks + 2 * tg;
        float2 f0 = *reinterpret_cast<const float2*>(feat + (r0    ) * D + k0    );
        float2 f1 = *reinterpret_cast<const float2*>(feat + (r0 + 8) * D + k0    );
        float2 f2 = *reinterpret_cast<const float2*>(feat + (r0    ) * D + k0 + 8);
        float2 f3 = *reinterpret_cast<const float2*>(feat + (r0 + 8) * D + k0 + 8);
        uint32_t a0 = pack_h2(f0.x, f0.y);
        uint32_t a1 = pack_h2(f1.x, f1.y);
        uint32_t a2 = pack_h2(f2.x, f2.y);
        uint32_t a3 = pack_h2(f3.x, f3.y);
#pragma unroll
        for (int np = 0; np < 8; np++) {
            uint4 b = g_wfrag[ks * 256 + np * 32 + lane];
            mma_f16(acc[2 * np][0], acc[2 * np][1], acc[2 * np][2], acc[2 * np][3],
                    a0, a1, a2, a3, b.x, b.y);
            mma_f16(acc[2 * np + 1][0], acc[2 * np + 1][1],
                    acc[2 * np + 1][2], acc[2 * np + 1][3],
                    a0, a1, a2, a3, b.z, b.w);
        }
    }

#pragma unroll
    for (int nt = 0; nt < 16; nt++) {
        int c = nt * 8 + 2 * tg;
        *reinterpret_cast<uint32_t*>(g_h16 + (r0    ) * D + c) =
            pack_h2(acc[nt][0], acc[nt][1]);
        *reinterpret_cast<uint32_t*>(g_h16 + (r0 + 8) * D + c) =
            pack_h2(acc[nt][2], acc[nt][3]);
    }
}

__global__ void __launch_bounds__(256) fused_gemm_fill_kernel(
    const float* __restrict__ feat, const int* __restrict__ ei)
{
    if (blockIdx.x < GEMM_BLOCKS) {
        int gw = blockIdx.x * 8 + (threadIdx.x >> 5);
        if (gw < GEMM_WARPS)
            gemm_warp_body(gw, threadIdx.x & 31, feat);
    } else {
        int i = (blockIdx.x - GEMM_BLOCKS) * 256 + threadIdx.x;
        if (i < N_EDGES / 4) {
            int4 s = reinterpret_cast<const int4*>(ei)[i];
            int4 d = reinterpret_cast<const int4*>(ei + N_EDGES)[i];
            int p0 = atomicAdd(&g_cursor[d.x], 1);
            int p1 = atomicAdd(&g_cursor[d.y], 1);
            int p2 = atomicAdd(&g_cursor[d.z], 1);
            int p3 = atomicAdd(&g_cursor[d.w], 1);
            fill_one(s.x, d.x, p0);
            fill_one(s.y, d.y, p1);
            fill_one(s.z, d.z, p2);
            fill_one(s.w, d.w, p3);
        }
    }
}

// ---------------------------------------------------------------------------
// 3) gather: warp-per-node, int4 bin loads, fp32 adds, + bias, relu, store.
// ---------------------------------------------------------------------------
__device__ __forceinline__ void acc_add(float4& a, uint2 u) {
    __half2 h0 = *reinterpret_cast<__half2*>(&u.x);
    __half2 h1 = *reinterpret_cast<__half2*>(&u.y);
    float2 f0 = __half22float2(h0);
    float2 f1 = __half22float2(h1);
    a.x += f0.x; a.y += f0.y; a.z += f1.x; a.w += f1.y;
}

__global__ void __launch_bounds__(256) gather_kernel(
    const float* __restrict__ bias, float* __restrict__ out)
{
    int warp = (blockIdx.x * blockDim.x + threadIdx.x) >> 5;
    int lane = threadIdx.x & 31;
    if (warp >= N_NODES) return;

    const uint2* f = reinterpret_cast<const uint2*>(g_h16);   // 32 uint2/row

    int degf = g_cursor[warp];
    int deg  = min(degf, CAP);
    const int4* bin4 = reinterpret_cast<const int4*>(&g_bins[warp * CAP]);

    float4 acc = make_float4(0.f, 0.f, 0.f, 0.f);

    int ng = deg >> 2;
    int g  = 0;
    for (; g + 2 <= ng; g += 2) {            // 8 edges in flight
        int4 sa = bin4[g];
        int4 sb = bin4[g + 1];
        uint2 u0 = f[sa.x * 32 + lane];
        uint2 u1 = f[sa.y * 32 + lane];
        uint2 u2 = f[sa.z * 32 + lane];
        uint2 u3 = f[sa.w * 32 + lane];
        uint2 u4 = f[sb.x * 32 + lane];
        uint2 u5 = f[sb.y * 32 + lane];
        uint2 u6 = f[sb.z * 32 + lane];
        uint2 u7 = f[sb.w * 32 + lane];
        acc_add(acc, u0); acc_add(acc, u1);
        acc_add(acc, u2); acc_add(acc, u3);
        acc_add(acc, u4); acc_add(acc, u5);
        acc_add(acc, u6); acc_add(acc, u7);
    }
    for (; g < ng; g++) {
        int4 s = bin4[g];
        uint2 u0 = f[s.x * 32 + lane];
        uint2 u1 = f[s.y * 32 + lane];
        uint2 u2 = f[s.z * 32 + lane];
        uint2 u3 = f[s.w * 32 + lane];
        acc_add(acc, u0); acc_add(acc, u1);
        acc_add(acc, u2); acc_add(acc, u3);
    }
    for (int e = ng * 4; e < deg; e++) {
        uint2 u = f[g_bins[warp * CAP + e] * 32 + lane];
        acc_add(acc, u);
    }

    if (degf > CAP) {                 // inline overflow fixup (expected never)
        int cnt = g_ovf_cnt;
        for (int j = 0; j < cnt; j++) {
            int2 sd = g_ovf[j];
            if (sd.y == warp) {
                uint2 u = f[sd.x * 32 + lane];
                acc_add(acc, u);
            }
        }
    }

    float4 bv = *reinterpret_cast<const float4*>(bias + lane * 4);
    float4 r;
    r.x = fmaxf(acc.x + bv.x, 0.f);
    r.y = fmaxf(acc.y + bv.y, 0.f);
    r.z = fmaxf(acc.z + bv.z, 0.f);
    r.w = fmaxf(acc.w + bv.w, 0.f);
    reinterpret_cast<float4*>(out)[warp * 32 + lane] = r;
}

// ---------------------------------------------------------------------------
extern "C" void kernel_launch(void* const* d_in, const int* in_sizes, int n_in,
                              void* d_out, int out_size)
{
    const float* feature = (const float*)d_in[0];   // [50000,128]
    const float* Wm      = (const float*)d_in[1];   // [128,128]
    const float* bias    = (const float*)d_in[2];   // [128]
    const int*   ei      = (const int*)  d_in[3];   // [2,800000]
    float*       out     = (float*)d_out;           // [50000,128]

    (void)in_sizes; (void)n_in; (void)out_size;

    prep_kernel<<<(N_NODES + 255) / 256, 256>>>(Wm);
    fused_gemm_fill_kernel<<<GEMM_BLOCKS + FILL_BLOCKS, 256>>>(feature, ei);
    {
        int total_threads = N_NODES * 32;
        gather_kernel<<<(total_threads + 255) / 256, 256>>>(bias, out);
    }
}